// round 6
// baseline (speedup 1.0000x reference)
#include <cuda_runtime.h>
#include <math.h>
#include <stdint.h>

#define N_MET 250000
#define N_RXN 500000
#define E_SUB 2000000
#define E_ALL 4000000
#define DT    0.01f
#define NB1   489   /* ceil(N_RXN/1024) */

// ---------------- constant weights (16B aligned for paired loads) ----------------
__constant__ __align__(16) float cW1[128];   // [2][64]: [j]=W1[0][j] (conc), [64+j]=W1[1][j] (sto)
__constant__ __align__(16) float cb1[64];
__constant__ __align__(16) float cW2[2048];  // [64][32]
__constant__ __align__(16) float cb2[32];
__constant__ __align__(16) float cW3[2048];  // [32][64]
__constant__ __align__(16) float cb3[64];
__constant__ __align__(16) float cW4[64];
__constant__ __align__(16) float cb4c[1];

// ---------------- device scratch (zero at module load) ----------------
__device__ float  g_conc[N_MET];
__device__ float  g_total[N_MET];                 // reset by k_metscale
__device__ float  g_met_scale[N_MET];
__device__ int    g_count[N_RXN];                 // reset by k_scan
__device__ int    g_offset[N_RXN + 1];
__device__ int    g_cursor[N_RXN];
__device__ int    g_ticket;                       // reset by k_hist
__device__ volatile unsigned long long g_pack[NB1]; // (val<<2)|status, reset by k_hist
__device__ float4 g_perm[E_SUB];                  // (conc, sto, met-as-float-bits, 0)
__device__ float  g_v[N_RXN];

// ---------------- helpers ----------------
__device__ __forceinline__ float tanha(float x) {
    float t; asm("tanh.approx.f32 %0, %1;" : "=f"(t) : "f"(x)); return t;
}
__device__ __forceinline__ uint64_t pk2(float lo, float hi) {
    uint64_t r; asm("mov.b64 %0, {%1, %2};" : "=l"(r) : "f"(lo), "f"(hi)); return r;
}
__device__ __forceinline__ void upk2(float& lo, float& hi, uint64_t v) {
    asm("mov.b64 {%0, %1}, %2;" : "=f"(lo), "=f"(hi) : "l"(v));
}
__device__ __forceinline__ uint64_t fma2(uint64_t a, uint64_t b, uint64_t c) {
    uint64_t d; asm("fma.rn.f32x2 %0, %1, %2, %3;" : "=l"(d) : "l"(a), "l"(b), "l"(c)); return d;
}
__device__ __forceinline__ uint64_t add2(uint64_t a, uint64_t b) {
    uint64_t d; asm("add.rn.f32x2 %0, %1, %2;" : "=l"(d) : "l"(a), "l"(b)); return d;
}
__device__ __forceinline__ uint64_t mul2(uint64_t a, uint64_t b) {
    uint64_t d; asm("mul.rn.f32x2 %0, %1, %2;" : "=l"(d) : "l"(a), "l"(b)); return d;
}
__device__ __forceinline__ uint64_t cpair(const float* p) {   // uniform 64-bit const load
    return *reinterpret_cast<const uint64_t*>(p);
}

// ---------------- launch 0: histogram + init/reset ----------------
__global__ void k_hist(const int* __restrict__ rxn_sub,
                       const float* __restrict__ x,
                       float* __restrict__ out) {
    int e = blockIdx.x * blockDim.x + threadIdx.x;
    if (e == 0) g_ticket = 0;
    if (e < NB1) g_pack[e] = 0ull;
    if (e < N_MET) {
        g_conc[e] = x[e * 8 + 3];
        out[e]    = 0.0f;
    }
    if (e < E_SUB) atomicAdd(&g_count[rxn_sub[e]], 1);
}

// ---------------- launch 1: single-pass decoupled-lookback scan ----------------
__global__ void k_scan() {
    __shared__ int sh[1024];
    __shared__ int s_bid;
    __shared__ int s_prefix;
    int t = threadIdx.x;
    if (t == 0) s_bid = atomicAdd(&g_ticket, 1);
    __syncthreads();
    int bid = s_bid;
    int i = bid * 1024 + t;
    int c = (i < N_RXN) ? g_count[i] : 0;
    sh[t] = c;
    __syncthreads();
    for (int off = 1; off < 1024; off <<= 1) {
        int add = (t >= off) ? sh[t - off] : 0;
        __syncthreads();
        sh[t] += add;
        __syncthreads();
    }
    if (t == 0) {
        int total = sh[1023];
        if (bid == 0) {
            g_pack[0] = (((unsigned long long)total) << 2) | 2ull;
            s_prefix = 0;
        } else {
            g_pack[bid] = (((unsigned long long)total) << 2) | 1ull;
            int ex = 0;
            int p = bid - 1;
            while (true) {
                unsigned long long v;
                do { v = g_pack[p]; } while ((v & 3ull) == 0ull);
                ex += (int)(v >> 2);
                if ((v & 3ull) == 2ull) break;
                --p;
            }
            g_pack[bid] = (((unsigned long long)(ex + total)) << 2) | 2ull;
            s_prefix = ex;
        }
    }
    __syncthreads();
    if (i < N_RXN) {
        int excl = s_prefix + sh[t] - c;
        g_offset[i] = excl;
        g_cursor[i] = excl;
        g_count[i]  = 0;                    // reset for next replay
        if (i == N_RXN - 1) g_offset[N_RXN] = excl + c;
    }
}

// ---------------- launch 2: scatter edges into reaction-grouped float4 records ----------------
__global__ void k_scatter(const int* __restrict__ met_sub,
                          const int* __restrict__ rxn_sub,
                          const float* __restrict__ sto_sub) {
    int e = blockIdx.x * blockDim.x + threadIdx.x;
    if (e >= E_SUB) return;
    int r = rxn_sub[e];
    int m = met_sub[e];
    int p = atomicAdd(&g_cursor[r], 1);
    g_perm[p] = make_float4(g_conc[m], sto_sub[e], __int_as_float(m), 0.0f);
}

// ---------------- launch 3 (ncu-captured): fused per-reaction MLP + consumption ----------------
__global__ void __launch_bounds__(128) k_rxn(const float* __restrict__ log_k) {
    int r = blockIdx.x * blockDim.x + threadIdx.x;
    if (r >= N_RXN) return;
    int beg = g_offset[r];
    int end = g_offset[r + 1];
    float n = (float)(end - beg);

    // ---- h[32] as 16 packed pairs; init with n*b2 ----
    uint64_t n2 = pk2(n, n);
    uint64_t h2[16];
#pragma unroll
    for (int q = 0; q < 16; q++) h2[q] = mul2(n2, cpair(&cb2[2 * q]));

    // ---- phase 2a+2b fused, 4 chunks of 16 hidden units (8 pairs) ----
    // keeps T footprint at 16 regs; edge records L1-hot after first chunk
    for (int ch = 0; ch < 4; ++ch) {
        int jb = ch * 16;
        uint64_t T2[8];
#pragma unroll
        for (int p = 0; p < 8; p++) T2[p] = 0ull;

        for (int i = beg; i < end; ++i) {
            float4 ed = __ldg(&g_perm[i]);
            uint64_t c2 = pk2(ed.x, ed.x);
            uint64_t s2 = pk2(ed.y, ed.y);
#pragma unroll
            for (int p = 0; p < 8; p++) {
                int j = jb + 2 * p;
                uint64_t z2 = fma2(s2, cpair(&cW1[64 + j]), cpair(&cb1[j]));
                z2 = fma2(c2, cpair(&cW1[j]), z2);
                float z0, z1; upk2(z0, z1, z2);
                T2[p] = add2(T2[p], pk2(tanha(z0), tanha(z1)));
            }
        }
        // fold chunk into h2
#pragma unroll
        for (int p = 0; p < 8; p++) {
            int j = jb + 2 * p;
            float ta, tb; upk2(ta, tb, T2[p]);
            uint64_t ta2 = pk2(ta, ta), tb2 = pk2(tb, tb);
#pragma unroll
            for (int q = 0; q < 16; q++) {
                h2[q] = fma2(ta2, cpair(&cW2[j * 32 + 2 * q]), h2[q]);
                h2[q] = fma2(tb2, cpair(&cW2[(j + 1) * 32 + 2 * q]), h2[q]);
            }
        }
    }

    // ---- unpack h to scalars ----
    float h[32];
#pragma unroll
    for (int q = 0; q < 16; q++) upk2(h[2 * q], h[2 * q + 1], h2[q]);

    // ---- phase 3: rolling pair accumulator over 32 output-pairs ----
    float racc = cb4c[0];
#pragma unroll 4
    for (int jp = 0; jp < 32; ++jp) {
        uint64_t a2 = cpair(&cb3[2 * jp]);
#pragma unroll
        for (int k = 0; k < 32; ++k) {
            uint64_t hk2 = pk2(h[k], h[k]);
            a2 = fma2(hk2, cpair(&cW3[k * 64 + 2 * jp]), a2);
        }
        float a0, a1; upk2(a0, a1, a2);
        racc = fmaf(tanha(a0), cW4[2 * jp], racc);
        racc = fmaf(tanha(a1), cW4[2 * jp + 1], racc);
    }

    // v = 10^log_k * softplus(racc)
    float sp = fmaxf(racc, 0.0f) + log1pf(__expf(-fabsf(racc)));
    float kk = __expf(log_k[r] * 2.302585093f);
    float v = kk * sp;
    g_v[r] = v;

    // fused consumption scatter (edge records are L1-hot)
    float vdt = v * DT;
    for (int i = beg; i < end; ++i) {
        float4 ed = g_perm[i];
        atomicAdd(&g_total[__float_as_int(ed.z)], ed.y * vdt);
    }
}

// ---------------- launch 4: per-metabolite scale (+ reset) ----------------
__global__ void k_metscale() {
    int i = blockIdx.x * blockDim.x + threadIdx.x;
    if (i >= N_MET) return;
    float t = g_total[i];
    float c = g_conc[i];
    g_met_scale[i] = (t > 1e-12f) ? fminf(c / t, 1.0f) : 1.0f;
    g_total[i] = 0.0f;                               // reset for next replay
}

// ---------------- launch 5: per-reaction min scale ----------------
__global__ void k_vscale() {
    int r = blockIdx.x * blockDim.x + threadIdx.x;
    if (r >= N_RXN) return;
    int beg = g_offset[r];
    int end = g_offset[r + 1];
    float m = 1.0f;
    for (int i = beg; i < end; ++i)
        m = fminf(m, g_met_scale[__float_as_int(g_perm[i].z)]);
    g_v[r] *= m;
}

// ---------------- launch 6: final scatter into dxdt ----------------
__global__ void k_out(const int* __restrict__ met_all,
                      const int* __restrict__ rxn_all,
                      const float* __restrict__ sto_all,
                      float* __restrict__ out) {
    int e = blockIdx.x * blockDim.x + threadIdx.x;
    if (e >= E_ALL) return;
    float contrib = sto_all[e] * __ldg(&g_v[rxn_all[e]]);
    atomicAdd(&out[met_all[e]], contrib);
}

extern "C" void kernel_launch(void* const* d_in, const int* in_sizes, int n_in,
                              void* d_out, int out_size) {
    const float* x       = (const float*)d_in[0];
    const int*   met_sub = (const int*)d_in[1];
    const int*   rxn_sub = (const int*)d_in[2];
    const float* sto_sub = (const float*)d_in[3];
    const int*   met_all = (const int*)d_in[4];
    const int*   rxn_all = (const int*)d_in[5];
    const float* sto_all = (const float*)d_in[6];
    const float* log_k   = (const float*)d_in[15];
    float* out = (float*)d_out;

    cudaMemcpyToSymbolAsync(cW1,  d_in[7],  128  * sizeof(float), 0, cudaMemcpyDeviceToDevice, 0);
    cudaMemcpyToSymbolAsync(cb1,  d_in[8],  64   * sizeof(float), 0, cudaMemcpyDeviceToDevice, 0);
    cudaMemcpyToSymbolAsync(cW2,  d_in[9],  2048 * sizeof(float), 0, cudaMemcpyDeviceToDevice, 0);
    cudaMemcpyToSymbolAsync(cb2,  d_in[10], 32   * sizeof(float), 0, cudaMemcpyDeviceToDevice, 0);
    cudaMemcpyToSymbolAsync(cW3,  d_in[11], 2048 * sizeof(float), 0, cudaMemcpyDeviceToDevice, 0);
    cudaMemcpyToSymbolAsync(cb3,  d_in[12], 64   * sizeof(float), 0, cudaMemcpyDeviceToDevice, 0);
    cudaMemcpyToSymbolAsync(cW4,  d_in[13], 64   * sizeof(float), 0, cudaMemcpyDeviceToDevice, 0);
    cudaMemcpyToSymbolAsync(cb4c, d_in[14], 1    * sizeof(float), 0, cudaMemcpyDeviceToDevice, 0);

    k_hist    <<<(E_SUB + 255) / 256, 256>>>(rxn_sub, x, out);               // 0
    k_scan    <<<NB1, 1024>>>();                                             // 1
    k_scatter <<<(E_SUB + 255) / 256, 256>>>(met_sub, rxn_sub, sto_sub);     // 2
    k_rxn     <<<(N_RXN + 127) / 128, 128>>>(log_k);                         // 3 <- profiled
    k_metscale<<<(N_MET + 255) / 256, 256>>>();                              // 4
    k_vscale  <<<(N_RXN + 255) / 256, 256>>>();                              // 5
    k_out     <<<(E_ALL + 255) / 256, 256>>>(met_all, rxn_all, sto_all, out);// 6
}

// round 7
// speedup vs baseline: 3.9960x; 3.9960x over previous
#include <cuda_runtime.h>
#include <math.h>
#include <stdint.h>

#define N_MET 250000
#define N_RXN 500000
#define E_SUB 2000000
#define E_ALL 4000000
#define DT    0.01f
#define NB1   489   /* ceil(N_RXN/1024) */

// ---------------- constant weights (16B aligned for paired loads) ----------------
__constant__ __align__(16) float cW1[128];   // [2][64]: [j]=W1[0][j] (conc), [64+j]=W1[1][j] (sto)
__constant__ __align__(16) float cb1[64];
__constant__ __align__(16) float cW2[2048];  // [64][32]
__constant__ __align__(16) float cb2[32];
__constant__ __align__(16) float cW3[2048];  // [32][64]
__constant__ __align__(16) float cb3[64];
__constant__ __align__(16) float cW4[64];
__constant__ __align__(16) float cb4c[1];

// ---------------- device scratch (zero at module load) ----------------
__device__ float  g_conc[N_MET];
__device__ float  g_total[N_MET];                 // reset by k_metscale
__device__ float  g_met_scale[N_MET];
__device__ int    g_count[N_RXN];                 // reset by k_scan
__device__ int    g_offset[N_RXN + 1];
__device__ int    g_cursor[N_RXN];
__device__ int    g_ticket;                       // reset by k_hist
__device__ volatile unsigned long long g_pack[NB1]; // (val<<2)|status, reset by k_hist
__device__ float4 g_perm[E_SUB];                  // (conc, sto, met-as-float-bits, 0)
__device__ float  g_v[N_RXN];

// ---------------- helpers ----------------
__device__ __forceinline__ float tanha(float x) {
    float t; asm("tanh.approx.f32 %0, %1;" : "=f"(t) : "f"(x)); return t;
}
__device__ __forceinline__ uint64_t pk2(float lo, float hi) {
    uint64_t r; asm("mov.b64 %0, {%1, %2};" : "=l"(r) : "f"(lo), "f"(hi)); return r;
}
__device__ __forceinline__ void upk2(float& lo, float& hi, uint64_t v) {
    asm("mov.b64 {%0, %1}, %2;" : "=f"(lo), "=f"(hi) : "l"(v));
}
__device__ __forceinline__ uint64_t fma2(uint64_t a, uint64_t b, uint64_t c) {
    uint64_t d; asm("fma.rn.f32x2 %0, %1, %2, %3;" : "=l"(d) : "l"(a), "l"(b), "l"(c)); return d;
}
__device__ __forceinline__ uint64_t add2(uint64_t a, uint64_t b) {
    uint64_t d; asm("add.rn.f32x2 %0, %1, %2;" : "=l"(d) : "l"(a), "l"(b)); return d;
}
__device__ __forceinline__ uint64_t mul2(uint64_t a, uint64_t b) {
    uint64_t d; asm("mul.rn.f32x2 %0, %1, %2;" : "=l"(d) : "l"(a), "l"(b)); return d;
}
__device__ __forceinline__ uint64_t cpair(const float* p) {   // 64-bit const load (static offset!)
    return *reinterpret_cast<const uint64_t*>(p);
}

// ---------------- launch 0: histogram + init/reset ----------------
__global__ void k_hist(const int* __restrict__ rxn_sub,
                       const float* __restrict__ x,
                       float* __restrict__ out) {
    int e = blockIdx.x * blockDim.x + threadIdx.x;
    if (e == 0) g_ticket = 0;
    if (e < NB1) g_pack[e] = 0ull;
    if (e < N_MET) {
        g_conc[e] = x[e * 8 + 3];
        out[e]    = 0.0f;
    }
    if (e < E_SUB) atomicAdd(&g_count[rxn_sub[e]], 1);
}

// ---------------- launch 1: single-pass decoupled-lookback scan ----------------
__global__ void k_scan() {
    __shared__ int sh[1024];
    __shared__ int s_bid;
    __shared__ int s_prefix;
    int t = threadIdx.x;
    if (t == 0) s_bid = atomicAdd(&g_ticket, 1);
    __syncthreads();
    int bid = s_bid;
    int i = bid * 1024 + t;
    int c = (i < N_RXN) ? g_count[i] : 0;
    sh[t] = c;
    __syncthreads();
    for (int off = 1; off < 1024; off <<= 1) {
        int add = (t >= off) ? sh[t - off] : 0;
        __syncthreads();
        sh[t] += add;
        __syncthreads();
    }
    if (t == 0) {
        int total = sh[1023];
        if (bid == 0) {
            g_pack[0] = (((unsigned long long)total) << 2) | 2ull;
            s_prefix = 0;
        } else {
            g_pack[bid] = (((unsigned long long)total) << 2) | 1ull;
            int ex = 0;
            int p = bid - 1;
            while (true) {
                unsigned long long v;
                do { v = g_pack[p]; } while ((v & 3ull) == 0ull);
                ex += (int)(v >> 2);
                if ((v & 3ull) == 2ull) break;
                --p;
            }
            g_pack[bid] = (((unsigned long long)(ex + total)) << 2) | 2ull;
            s_prefix = ex;
        }
    }
    __syncthreads();
    if (i < N_RXN) {
        int excl = s_prefix + sh[t] - c;
        g_offset[i] = excl;
        g_cursor[i] = excl;
        g_count[i]  = 0;                    // reset for next replay
        if (i == N_RXN - 1) g_offset[N_RXN] = excl + c;
    }
}

// ---------------- launch 2: scatter edges into reaction-grouped float4 records ----------------
__global__ void k_scatter(const int* __restrict__ met_sub,
                          const int* __restrict__ rxn_sub,
                          const float* __restrict__ sto_sub) {
    int e = blockIdx.x * blockDim.x + threadIdx.x;
    if (e >= E_SUB) return;
    int r = rxn_sub[e];
    int m = met_sub[e];
    int p = atomicAdd(&g_cursor[r], 1);
    g_perm[p] = make_float4(g_conc[m], sto_sub[e], __int_as_float(m), 0.0f);
}

// ---------------- launch 3 (ncu-captured): fused per-reaction MLP + consumption ----------------
__global__ void __launch_bounds__(128) k_rxn(const float* __restrict__ log_k) {
    int r = blockIdx.x * blockDim.x + threadIdx.x;
    if (r >= N_RXN) return;
    int beg = g_offset[r];
    int end = g_offset[r + 1];
    float n = (float)(end - beg);

    // ---- h[32] as 16 packed pairs; init with n*b2 ----
    uint64_t n2 = pk2(n, n);
    uint64_t h2[16];
#pragma unroll
    for (int q = 0; q < 16; q++) h2[q] = mul2(n2, cpair(&cb2[2 * q]));

    // ---- phase 2a+2b fused: 4 FULLY-UNROLLED chunks of 16 hidden units ----
    // ch is compile-time => all constant-bank offsets static (LDCU/imm, no computed LDC).
    // T2 footprint = 8 pairs = 16 regs. Edge records L1-hot after chunk 0.
#pragma unroll
    for (int ch = 0; ch < 4; ++ch) {
        uint64_t T2[8];
#pragma unroll
        for (int p = 0; p < 8; p++) T2[p] = 0ull;

        for (int i = beg; i < end; ++i) {
            float4 ed = __ldg(&g_perm[i]);
            uint64_t c2 = pk2(ed.x, ed.x);
            uint64_t s2 = pk2(ed.y, ed.y);
#pragma unroll
            for (int p = 0; p < 8; p++) {
                const int j = ch * 16 + 2 * p;            // compile-time constant
                uint64_t z2 = fma2(s2, cpair(&cW1[64 + j]), cpair(&cb1[j]));
                z2 = fma2(c2, cpair(&cW1[j]), z2);
                float z0, z1; upk2(z0, z1, z2);
                T2[p] = add2(T2[p], pk2(tanha(z0), tanha(z1)));
            }
        }
        // fold chunk into h2 (static offsets)
#pragma unroll
        for (int p = 0; p < 8; p++) {
            const int j = ch * 16 + 2 * p;                // compile-time constant
            float ta, tb; upk2(ta, tb, T2[p]);
            uint64_t ta2 = pk2(ta, ta), tb2 = pk2(tb, tb);
#pragma unroll
            for (int q = 0; q < 16; q++) {
                h2[q] = fma2(ta2, cpair(&cW2[j * 32 + 2 * q]), h2[q]);
                h2[q] = fma2(tb2, cpair(&cW2[(j + 1) * 32 + 2 * q]), h2[q]);
            }
        }
    }

    // ---- unpack h to scalars ----
    float h[32];
#pragma unroll
    for (int q = 0; q < 16; q++) upk2(h[2 * q], h[2 * q + 1], h2[q]);

    // ---- phase 3: 2 FULLY-UNROLLED halves of 16 pair-accumulators (ILP 16) ----
    float racc = cb4c[0];
#pragma unroll
    for (int half = 0; half < 2; ++half) {
        uint64_t a2[16];
#pragma unroll
        for (int p = 0; p < 16; p++) a2[p] = cpair(&cb3[half * 32 + 2 * p]);
#pragma unroll
        for (int k = 0; k < 32; ++k) {
            uint64_t hk2 = pk2(h[k], h[k]);
#pragma unroll
            for (int p = 0; p < 16; p++) {
                const int jp = half * 32 + 2 * p;         // compile-time constant
                a2[p] = fma2(hk2, cpair(&cW3[k * 64 + jp]), a2[p]);
            }
        }
#pragma unroll
        for (int p = 0; p < 16; p++) {
            const int jp = half * 32 + 2 * p;
            float a0, a1; upk2(a0, a1, a2[p]);
            racc = fmaf(tanha(a0), cW4[jp], racc);
            racc = fmaf(tanha(a1), cW4[jp + 1], racc);
        }
    }

    // v = 10^log_k * softplus(racc)
    float sp = fmaxf(racc, 0.0f) + log1pf(__expf(-fabsf(racc)));
    float kk = __expf(log_k[r] * 2.302585093f);
    float v = kk * sp;
    g_v[r] = v;

    // fused consumption scatter (edge records are L1-hot)
    float vdt = v * DT;
    for (int i = beg; i < end; ++i) {
        float4 ed = g_perm[i];
        atomicAdd(&g_total[__float_as_int(ed.z)], ed.y * vdt);
    }
}

// ---------------- launch 4: per-metabolite scale (+ reset) ----------------
__global__ void k_metscale() {
    int i = blockIdx.x * blockDim.x + threadIdx.x;
    if (i >= N_MET) return;
    float t = g_total[i];
    float c = g_conc[i];
    g_met_scale[i] = (t > 1e-12f) ? fminf(c / t, 1.0f) : 1.0f;
    g_total[i] = 0.0f;                               // reset for next replay
}

// ---------------- launch 5: per-reaction min scale ----------------
__global__ void k_vscale() {
    int r = blockIdx.x * blockDim.x + threadIdx.x;
    if (r >= N_RXN) return;
    int beg = g_offset[r];
    int end = g_offset[r + 1];
    float m = 1.0f;
    for (int i = beg; i < end; ++i)
        m = fminf(m, g_met_scale[__float_as_int(g_perm[i].z)]);
    g_v[r] *= m;
}

// ---------------- launch 6: final scatter into dxdt ----------------
__global__ void k_out(const int* __restrict__ met_all,
                      const int* __restrict__ rxn_all,
                      const float* __restrict__ sto_all,
                      float* __restrict__ out) {
    int e = blockIdx.x * blockDim.x + threadIdx.x;
    if (e >= E_ALL) return;
    float contrib = sto_all[e] * __ldg(&g_v[rxn_all[e]]);
    atomicAdd(&out[met_all[e]], contrib);
}

extern "C" void kernel_launch(void* const* d_in, const int* in_sizes, int n_in,
                              void* d_out, int out_size) {
    const float* x       = (const float*)d_in[0];
    const int*   met_sub = (const int*)d_in[1];
    const int*   rxn_sub = (const int*)d_in[2];
    const float* sto_sub = (const float*)d_in[3];
    const int*   met_all = (const int*)d_in[4];
    const int*   rxn_all = (const int*)d_in[5];
    const float* sto_all = (const float*)d_in[6];
    const float* log_k   = (const float*)d_in[15];
    float* out = (float*)d_out;

    cudaMemcpyToSymbolAsync(cW1,  d_in[7],  128  * sizeof(float), 0, cudaMemcpyDeviceToDevice, 0);
    cudaMemcpyToSymbolAsync(cb1,  d_in[8],  64   * sizeof(float), 0, cudaMemcpyDeviceToDevice, 0);
    cudaMemcpyToSymbolAsync(cW2,  d_in[9],  2048 * sizeof(float), 0, cudaMemcpyDeviceToDevice, 0);
    cudaMemcpyToSymbolAsync(cb2,  d_in[10], 32   * sizeof(float), 0, cudaMemcpyDeviceToDevice, 0);
    cudaMemcpyToSymbolAsync(cW3,  d_in[11], 2048 * sizeof(float), 0, cudaMemcpyDeviceToDevice, 0);
    cudaMemcpyToSymbolAsync(cb3,  d_in[12], 64   * sizeof(float), 0, cudaMemcpyDeviceToDevice, 0);
    cudaMemcpyToSymbolAsync(cW4,  d_in[13], 64   * sizeof(float), 0, cudaMemcpyDeviceToDevice, 0);
    cudaMemcpyToSymbolAsync(cb4c, d_in[14], 1    * sizeof(float), 0, cudaMemcpyDeviceToDevice, 0);

    k_hist    <<<(E_SUB + 255) / 256, 256>>>(rxn_sub, x, out);               // 0
    k_scan    <<<NB1, 1024>>>();                                             // 1
    k_scatter <<<(E_SUB + 255) / 256, 256>>>(met_sub, rxn_sub, sto_sub);     // 2
    k_rxn     <<<(N_RXN + 127) / 128, 128>>>(log_k);                         // 3 <- profiled
    k_metscale<<<(N_MET + 255) / 256, 256>>>();                              // 4
    k_vscale  <<<(N_RXN + 255) / 256, 256>>>();                              // 5
    k_out     <<<(E_ALL + 255) / 256, 256>>>(met_all, rxn_all, sto_all, out);// 6
}